// round 10
// baseline (speedup 1.0000x reference)
#include <cuda_runtime.h>
#include <cuda_fp16.h>
#include <cstdint>
#include <cstddef>

#define T_STEPS 4
#define BATCH   8
#define C_DIM   384
#define H_DIM   1536
#define QKV_M   1152
#define N_SP    784
#define NH      8
#define HD      48
#define TB      32

// ---------------- scratch ----------------------------------------------------
__device__ __align__(256) float  g_pre [(size_t)TB*N_SP*H_DIM];
__device__ __align__(256) __half g_xh  [(size_t)TB*N_SP*C_DIM];
__device__ __align__(256) __half g_xl  [(size_t)TB*N_SP*C_DIM];
__device__ __align__(256) __half g_wqkvh[(size_t)QKV_M*C_DIM];
__device__ __align__(256) __half g_wqkvl[(size_t)QKV_M*C_DIM];
__device__ __align__(256) __half g_wph[(size_t)C_DIM*C_DIM];
__device__ __align__(256) __half g_wpl[(size_t)C_DIM*C_DIM];
__device__ __align__(256) __half g_w1h[(size_t)H_DIM*C_DIM];
__device__ __align__(256) __half g_w1l[(size_t)H_DIM*C_DIM];
__device__ __align__(256) __half g_w2h[(size_t)C_DIM*H_DIM];
__device__ __align__(256) __half g_w2l[(size_t)C_DIM*H_DIM];
__device__ __align__(256) float  g_offqkv[QKV_M];
__device__ __align__(256) float  g_offp[C_DIM];
__device__ __align__(256) float  g_off1[H_DIM];
__device__ __align__(256) float  g_off2[C_DIM];
__device__ __align__(256) __half g_qkv [(size_t)TB*N_SP*QKV_M];
__device__ __align__(256) float  g_M   [(size_t)TB*NH*HD*HD];
__device__ __align__(256) __half g_aspk[(size_t)TB*N_SP*C_DIM];
__device__ __align__(256) __half g_pspk[(size_t)TB*N_SP*C_DIM];
__device__ __align__(256) __half g_x1h [(size_t)TB*N_SP*C_DIM];
__device__ __align__(256) __half g_x1l [(size_t)TB*N_SP*C_DIM];
__device__ __align__(256) float  g_x1f [(size_t)TB*C_DIM*N_SP];
__device__ __align__(256) __half g_hspk[(size_t)TB*N_SP*H_DIM];
__device__ __align__(256) __half g_mspk[(size_t)TB*N_SP*C_DIM];

// ---------------- helpers ----------------------------------------------------
__device__ __forceinline__ uint32_t smem_u32(const void* p) {
    uint32_t a;
    asm("{ .reg .u64 t; cvta.to.shared.u64 t, %1; cvt.u32.u64 %0, t; }" : "=r"(a) : "l"(p));
    return a;
}
__device__ __forceinline__ void ldsm4(uint32_t* r, uint32_t addr) {
    asm volatile("ldmatrix.sync.aligned.m8n8.x4.shared.b16 {%0,%1,%2,%3}, [%4];"
        : "=r"(r[0]), "=r"(r[1]), "=r"(r[2]), "=r"(r[3]) : "r"(addr));
}
__device__ __forceinline__ void mma16816(float* d, const uint32_t* a, const uint32_t* b) {
    asm volatile("mma.sync.aligned.m16n8k16.row.col.f32.f16.f16.f32 "
        "{%0,%1,%2,%3}, {%4,%5,%6,%7}, {%8,%9}, {%0,%1,%2,%3};"
        : "+f"(d[0]), "+f"(d[1]), "+f"(d[2]), "+f"(d[3])
        : "r"(a[0]), "r"(a[1]), "r"(a[2]), "r"(a[3]), "r"(b[0]), "r"(b[1]));
}
__device__ __forceinline__ void cp16(uint32_t dst, const void* src, int szz) {
    asm volatile("cp.async.ca.shared.global [%0], [%1], 16, %2;"
                 :: "r"(dst), "l"(src), "r"(szz));
}
__device__ __forceinline__ void cp_commit() {
    asm volatile("cp.async.commit_group;" ::: "memory");
}
template<int N> __device__ __forceinline__ void cp_wait() {
    asm volatile("cp.async.wait_group %0;" :: "n"(N) : "memory");
}

// ---------------- weight fold + split ---------------------------------------
__device__ __forceinline__ void wsplit_one(const float* w, const float* bnp,
                                           const float* bias, __half* wh, __half* wl,
                                           float* off, int O, int C, int dstRow, int idx) {
    int o = idx / C, c = idx - o * C;
    float inv = bnp[o] / sqrtf(bnp[3*O + o] + 1e-5f);
    float wv = w[idx] * inv;
    __half h = __float2half_rn(wv);
    size_t d = (size_t)(dstRow + o) * C + c;
    wh[d] = h;
    wl[d] = __float2half_rn(wv - __half2float(h));
    if (c == 0) {
        float b = bias ? bias[c] : 0.0f;   // placeholder; fixed below
        (void)b;
    }
    if (c == 0) {
        float bb = bias ? bias[o] : 0.0f;
        off[dstRow + o] = (bb - bnp[2*O + o]) * inv + bnp[O + o];
    }
}

__global__ void wsplit_kernel(const float* __restrict__ w, const float* __restrict__ bnp,
                              const float* __restrict__ bias,
                              __half* __restrict__ wh, __half* __restrict__ wl,
                              float* __restrict__ off, int O, int C, int dstRow) {
    int idx = blockIdx.x * blockDim.x + threadIdx.x;
    if (idx >= O * C) return;
    wsplit_one(w, bnp, bias, wh, wl, off, O, C, dstRow, idx);
}

// 3 qkv weights in ONE launch (also puts the big GEMM at ncu's capture slot)
__global__ void wsplit3_kernel(const float* __restrict__ qw, const float* __restrict__ kw,
                               const float* __restrict__ vw, const float* __restrict__ qbn,
                               const float* __restrict__ kbn, const float* __restrict__ vbn,
                               __half* __restrict__ wh, __half* __restrict__ wl,
                               float* __restrict__ off) {
    const int per = C_DIM * C_DIM;
    int gidx = blockIdx.x * blockDim.x + threadIdx.x;
    if (gidx >= 3 * per) return;
    int wi = gidx / per, idx = gidx - wi * per;
    const float* w   = (wi == 0) ? qw  : (wi == 1) ? kw  : vw;
    const float* bnp = (wi == 0) ? qbn : (wi == 1) ? kbn : vbn;
    wsplit_one(w, bnp, nullptr, wh, wl, off, C_DIM, C_DIM, wi * C_DIM, idx);
}

// ---------------- x: [tb,C,N] f32 -> [tb,n,C] f16 h/l ------------------------
__global__ void xsplit_kernel(const float* __restrict__ x,
                              __half* __restrict__ xh, __half* __restrict__ xl) {
    __shared__ float t[32][33];
    int tb = blockIdx.z, c0 = blockIdx.x * 32, n0 = blockIdx.y * 32;
    int tx = threadIdx.x, ty = threadIdx.y;
    #pragma unroll
    for (int i = 0; i < 4; i++) {
        int cl = ty + i * 8, n = n0 + tx;
        t[cl][tx] = (n < N_SP) ? x[((size_t)tb * C_DIM + c0 + cl) * N_SP + n] : 0.0f;
    }
    __syncthreads();
    #pragma unroll
    for (int i = 0; i < 4; i++) {
        int nl = ty + i * 8, n = n0 + nl;
        if (n < N_SP) {
            float v = t[tx][nl];
            __half h = __float2half_rn(v);
            size_t d = ((size_t)tb * N_SP + n) * C_DIM + c0 + tx;
            xh[d] = h;
            xl[d] = __float2half_rn(v - __half2float(h));
        }
    }
}

// ---------------- pipelined HMMA GEMM (KC=32, 3-stage, 1 sync/chunk) ---------
// pre[tb,n,c] = sum_k Act[tb,n,k]*W[c,k] + off[c]
#define STRD 40
#define TILEB (128*STRD*2)        // 10240 B
#define STAGEB (4*TILEB)          // 40960
#define GSMEM (3*STAGEB)          // 122880
__global__ __launch_bounds__(256) void gemm_hmma(
    const __half* __restrict__ A0, const __half* __restrict__ A1,
    const __half* __restrict__ W0, const __half* __restrict__ W1,
    const float* __restrict__ off, float* __restrict__ pre,
    int K, int Mtot, int nsA)
{
    extern __shared__ char smraw[];
    const int tb = blockIdx.z;
    const int n0 = blockIdx.x * 128;
    const int m0 = blockIdx.y * 128;
    const int tid = threadIdx.x;
    const int lane = tid & 31, warp = tid >> 5;
    const int wn = (warp >> 2) * 64;
    const int wc = (warp & 3) * 32;
    const uint32_t smb = smem_u32(smraw);
    const __half* Wops[2] = {W0, W1};

    const int lrow = tid >> 1, lp = (tid & 1) * 16;
    const int nA = n0 + lrow;
    const int nAc = (nA < N_SP) ? nA : (N_SP - 1);
    const int aSz = (nA < N_SP) ? 16 : 0;
    const __half* aptr[2] = {
        A0 + ((size_t)tb * N_SP + nAc) * K,
        A1 + ((size_t)tb * N_SP + nAc) * K };

    float acc[4][4][4];
    #pragma unroll
    for (int mi = 0; mi < 4; mi++)
        #pragma unroll
        for (int cj = 0; cj < 4; cj++)
            #pragma unroll
            for (int r = 0; r < 4; r++) acc[mi][cj][r] = 0.0f;

    const int a_row = lane & 15;
    const int a_col = ((lane >> 4) & 1) * 8;
    const int w_row = ((lane >> 4) & 1) * 8 + (lane & 7);
    const int w_col = ((lane >> 3) & 1) * 8;

    #define LOADST(ST, K0)                                                          \
    {                                                                               \
        _Pragma("unroll")                                                           \
        for (int s = 0; s < 2; s++) {                                               \
            if (s < nsA) {                                                          \
                const __half* src = aptr[s] + (K0) + lp;                            \
                uint32_t dst = smb + (ST) * STAGEB + s * TILEB + (lrow * STRD + lp) * 2; \
                cp16(dst, src, aSz);                                                \
                cp16(dst + 16, src + 8, aSz);                                       \
            }                                                                       \
            const __half* wsrc = Wops[s] + (size_t)(m0 + lrow) * K + (K0) + lp;     \
            uint32_t wdst = smb + (ST) * STAGEB + (2 + s) * TILEB + (lrow * STRD + lp) * 2; \
            cp16(wdst, wsrc, 16);                                                   \
            cp16(wdst + 16, wsrc + 8, 16);                                          \
        }                                                                           \
        cp_commit();                                                                \
    }

    const int nch = K / 32;
    LOADST(0, 0)

    int st = 0, stNext = 1;
    for (int ch = 0; ch < nch; ch++) {
        if (ch + 1 < nch) {
            LOADST(stNext, (ch + 1) * 32)
            cp_wait<1>();
        } else {
            cp_wait<0>();
        }
        __syncthreads();   // single barrier per chunk (3-stage makes trailing sync unnecessary)

        #pragma unroll
        for (int ks = 0; ks < 2; ks++) {
            uint32_t wf[2][8];
            #pragma unroll
            for (int s = 0; s < 2; s++)
                #pragma unroll
                for (int hb = 0; hb < 2; hb++) {
                    uint32_t ad = smb + st * STAGEB + (2 + s) * TILEB
                        + ((wc + hb * 16 + w_row) * STRD + ks * 16 + w_col) * 2;
                    ldsm4(&wf[s][hb * 4], ad);
                }
            #pragma unroll
            for (int mi = 0; mi < 4; mi++) {
                uint32_t af[2][4];
                #pragma unroll
                for (int s = 0; s < 2; s++)
                    if (s < nsA) {
                        uint32_t ad = smb + st * STAGEB + s * TILEB
                            + ((wn + mi * 16 + a_row) * STRD + ks * 16 + a_col) * 2;
                        ldsm4(af[s], ad);
                    }
                #pragma unroll
                for (int cj = 0; cj < 4; cj++) {
                    mma16816(acc[mi][cj], af[0], &wf[0][cj * 2]);     // Ah*Wh
                    mma16816(acc[mi][cj], af[0], &wf[1][cj * 2]);     // Ah*Wl
                    if (nsA == 2)
                        mma16816(acc[mi][cj], af[1], &wf[0][cj * 2]); // Al*Wh
                }
            }
        }
        st = stNext;
        stNext = (stNext == 2) ? 0 : stNext + 1;
    }
    #undef LOADST

    // epilogue: add off, store fp32 preact
    #pragma unroll
    for (int mi = 0; mi < 4; mi++) {
        int rA = n0 + wn + mi * 16 + (lane >> 2);
        int rB = rA + 8;
        #pragma unroll
        for (int cj = 0; cj < 4; cj++) {
            int c = m0 + wc + cj * 8 + 2 * (lane & 3);
            float o0 = off[c], o1 = off[c + 1];
            if (rA < N_SP) {
                float2 v = {acc[mi][cj][0] + o0, acc[mi][cj][1] + o1};
                *(float2*)(pre + ((size_t)tb * N_SP + rA) * Mtot + c) = v;
            }
            if (rB < N_SP) {
                float2 v = {acc[mi][cj][2] + o0, acc[mi][cj][3] + o1};
                *(float2*)(pre + ((size_t)tb * N_SP + rB) * Mtot + c) = v;
            }
        }
    }
}

// ---------------- LIF over T=4 on [tb,n,M] layout (x2 vectorized) ------------
__global__ void lif_kernel(const float* __restrict__ pre, __half* __restrict__ spk,
                           int ept, float vth)
{
    int i = (blockIdx.x * blockDim.x + threadIdx.x) * 2;
    if (i >= ept) return;
    float v0 = 0.0f, v1 = 0.0f;
    #pragma unroll
    for (int t = 0; t < T_STEPS; t++) {
        float2 x = *(const float2*)(pre + i + (size_t)t * ept);
        v0 = __fadd_rn(v0, __fmul_rn(__fsub_rn(x.x, v0), 0.5f));
        v1 = __fadd_rn(v1, __fmul_rn(__fsub_rn(x.y, v1), 0.5f));
        float s0 = (v0 >= vth) ? 1.0f : 0.0f;
        float s1 = (v1 >= vth) ? 1.0f : 0.0f;
        __half2 sp = __floats2half2_rn(s0, s1);
        *(__half2*)(spk + i + (size_t)t * ept) = sp;
        if (s0 != 0.0f) v0 = 0.0f;
        if (s1 != 0.0f) v1 = 0.0f;
    }
}

// ---------------- attention: M = K^T V (exact ints) --------------------------
__global__ __launch_bounds__(256) void attn_m_kernel(const __half* __restrict__ qkv,
                                                     float* __restrict__ Mout) {
    __shared__ float Ks[64][HD];
    __shared__ float Vs[64][HD];
    const int zz = blockIdx.x, h = zz & 7, tb = zz >> 3;
    const int tid = threadIdx.x;
    const __half* Kb = qkv + (size_t)tb * N_SP * QKV_M + C_DIM + h * HD;
    const __half* Vb = qkv + (size_t)tb * N_SP * QKV_M + 2 * C_DIM + h * HD;
    float acc[9]; int di[9], ei[9];
    #pragma unroll
    for (int i = 0; i < 9; i++) {
        acc[i] = 0.0f;
        int p = tid + i * 256; di[i] = p / HD; ei[i] = p % HD;
    }
    for (int nn0 = 0; nn0 < N_SP; nn0 += 64) {
        for (int l = tid; l < 64 * HD; l += 256) {
            int r = l / HD, cc = l % HD, n = nn0 + r;
            float kv = 0.0f, vv = 0.0f;
            if (n < N_SP) {
                kv = __half2float(Kb[(size_t)n * QKV_M + cc]);
                vv = __half2float(Vb[(size_t)n * QKV_M + cc]);
            }
            Ks[r][cc] = kv; Vs[r][cc] = vv;
        }
        __syncthreads();
        #pragma unroll
        for (int i = 0; i < 9; i++) {
            float s = acc[i];
            #pragma unroll
            for (int nn = 0; nn < 64; nn++) s += Ks[nn][di[i]] * Vs[nn][ei[i]];
            acc[i] = s;
        }
        __syncthreads();
    }
    #pragma unroll
    for (int i = 0; i < 9; i++) Mout[(size_t)zz * (HD * HD) + tid + i * 256] = acc[i];
}

// ---------------- O = Q*M*0.25 + fused attn-LIF (vth=0.5) --------------------
__global__ __launch_bounds__(128) void attn_o_lif_kernel(const __half* __restrict__ qkv,
                                                         const float* __restrict__ Mbuf,
                                                         __half* __restrict__ aspk) {
    __shared__ float Ms[HD * HD];
    const int nt = blockIdx.x, h = blockIdx.y, b = blockIdx.z;
    const int tid = threadIdx.x;
    const int n = nt * 128 + tid;
    float v[HD];
    #pragma unroll
    for (int e = 0; e < HD; e++) v[e] = 0.0f;
    for (int t = 0; t < 4; t++) {
        int tb = t * BATCH + b;
        for (int l = tid; l < HD * HD; l += 128)
            Ms[l] = Mbuf[((size_t)tb * NH + h) * (HD * HD) + l];
        __syncthreads();
        if (n < N_SP) {
            const __half* Qp = qkv + ((size_t)tb * N_SP + n) * QKV_M + h * HD;
            float q[HD];
            #pragma unroll
            for (int d = 0; d < HD; d++) q[d] = __half2float(Qp[d]);
            __half* Op = aspk + ((size_t)tb * N_SP + n) * C_DIM + h * HD;
            #pragma unroll 4
            for (int e = 0; e < HD; e++) {
                float s = 0.0f;
                #pragma unroll
                for (int d = 0; d < HD; d++) s += q[d] * Ms[d * HD + e];
                float x = s * 0.25f;
                float ve = v[e];
                ve = __fadd_rn(ve, __fmul_rn(__fsub_rn(x, ve), 0.5f));
                float sp = (ve >= 0.5f) ? 1.0f : 0.0f;
                Op[e] = __float2half_rn(sp);
                v[e] = (sp != 0.0f) ? 0.0f : ve;
            }
        }
        __syncthreads();
    }
}

// ---------------- x1 = x + proj_spk -----------------------------------------
__global__ void x1_kernel(const float* __restrict__ x, const __half* __restrict__ pspk,
                          float* __restrict__ x1f,
                          __half* __restrict__ x1h, __half* __restrict__ x1l) {
    __shared__ float s[32][33];
    int tb = blockIdx.z, c0 = blockIdx.x * 32, n0 = blockIdx.y * 32;
    int tx = threadIdx.x, ty = threadIdx.y;
    #pragma unroll
    for (int i = 0; i < 4; i++) {
        int nl = ty + i * 8, n = n0 + nl;
        s[nl][tx] = (n < N_SP)
            ? __half2float(pspk[((size_t)tb * N_SP + n) * C_DIM + c0 + tx]) : 0.0f;
    }
    __syncthreads();
    #pragma unroll
    for (int i = 0; i < 4; i++) {
        int cl = ty + i * 8, n = n0 + tx;
        if (n < N_SP) {
            size_t xi = ((size_t)tb * C_DIM + c0 + cl) * N_SP + n;
            float val = x[xi] + s[tx][cl];
            x1f[xi] = val;
            s[tx][cl] = val;
        }
    }
    __syncthreads();
    #pragma unroll
    for (int i = 0; i < 4; i++) {
        int nl = ty + i * 8, n = n0 + nl;
        if (n < N_SP) {
            float val = s[nl][tx];
            __half h = __float2half_rn(val);
            size_t d = ((size_t)tb * N_SP + n) * C_DIM + c0 + tx;
            x1h[d] = h;
            x1l[d] = __float2half_rn(val - __half2float(h));
        }
    }
}

// ---------------- out = x1f + mspk^T ----------------------------------------
__global__ void final_kernel(const float* __restrict__ x1f, const __half* __restrict__ mspk,
                             float* __restrict__ out) {
    __shared__ float s[32][33];
    int tb = blockIdx.z, c0 = blockIdx.x * 32, n0 = blockIdx.y * 32;
    int tx = threadIdx.x, ty = threadIdx.y;
    #pragma unroll
    for (int i = 0; i < 4; i++) {
        int nl = ty + i * 8, n = n0 + nl;
        s[nl][tx] = (n < N_SP)
            ? __half2float(mspk[((size_t)tb * N_SP + n) * C_DIM + c0 + tx]) : 0.0f;
    }
    __syncthreads();
    #pragma unroll
    for (int i = 0; i < 4; i++) {
        int cl = ty + i * 8, n = n0 + tx;
        if (n < N_SP) {
            size_t xi = ((size_t)tb * C_DIM + c0 + cl) * N_SP + n;
            out[xi] = x1f[xi] + s[tx][cl];
        }
    }
}

// ---------------------------------------------------------------------------
extern "C" void kernel_launch(void* const* d_in, const int* in_sizes, int n_in,
                              void* d_out, int out_size) {
    const float* x      = (const float*)d_in[0];
    const float* q_w    = (const float*)d_in[1];
    const float* k_w    = (const float*)d_in[2];
    const float* v_w    = (const float*)d_in[3];
    const float* q_bn   = (const float*)d_in[4];
    const float* k_bn   = (const float*)d_in[5];
    const float* v_bn   = (const float*)d_in[6];
    const float* proj_w = (const float*)d_in[7];
    const float* proj_b = (const float*)d_in[8];
    const float* proj_bn= (const float*)d_in[9];
    const float* fc1_w  = (const float*)d_in[10];
    const float* fc1_b  = (const float*)d_in[11];
    const float* fc1_bn = (const float*)d_in[12];
    const float* fc2_w  = (const float*)d_in[13];
    const float* fc2_b  = (const float*)d_in[14];
    const float* fc2_bn = (const float*)d_in[15];
    float* out = (float*)d_out;

    cudaFuncSetAttribute(gemm_hmma, cudaFuncAttributeMaxDynamicSharedMemorySize, GSMEM);

    __half *xh, *xl, *wqkvh, *wqkvl, *wph, *wpl, *w1h, *w1l, *w2h, *w2l;
    __half *qkv, *aspk, *pspk, *x1h, *x1l, *hspk, *mspk;
    float *offqkv, *offp, *off1, *off2, *Mb, *x1f, *pre;
    cudaGetSymbolAddress((void**)&pre, g_pre);
    cudaGetSymbolAddress((void**)&xh, g_xh);       cudaGetSymbolAddress((void**)&xl, g_xl);
    cudaGetSymbolAddress((void**)&wqkvh, g_wqkvh); cudaGetSymbolAddress((void**)&wqkvl, g_wqkvl);
    cudaGetSymbolAddress((void**)&wph, g_wph);     cudaGetSymbolAddress((void**)&wpl, g_wpl);
    cudaGetSymbolAddress((void**)&w1h, g_w1h);     cudaGetSymbolAddress((void**)&w1l, g_w1l);
    cudaGetSymbolAddress((void**)&w2h, g_w2h);     cudaGetSymbolAddress((void**)&w2l, g_w2l);
    cudaGetSymbolAddress((void**)&offqkv, g_offqkv); cudaGetSymbolAddress((void**)&offp, g_offp);
    cudaGetSymbolAddress((void**)&off1, g_off1);   cudaGetSymbolAddress((void**)&off2, g_off2);
    cudaGetSymbolAddress((void**)&qkv, g_qkv);     cudaGetSymbolAddress((void**)&Mb, g_M);
    cudaGetSymbolAddress((void**)&aspk, g_aspk);   cudaGetSymbolAddress((void**)&pspk, g_pspk);
    cudaGetSymbolAddress((void**)&x1h, g_x1h);     cudaGetSymbolAddress((void**)&x1l, g_x1l);
    cudaGetSymbolAddress((void**)&x1f, g_x1f);
    cudaGetSymbolAddress((void**)&hspk, g_hspk);   cudaGetSymbolAddress((void**)&mspk, g_mspk);

    dim3 tb32(32, 8);
    dim3 tgrid(C_DIM / 32, (N_SP + 31) / 32, TB);

    // launches 1-5 (so ncu -s 5 -c 1 captures the qkv GEMM at slot 6)
    int wb3 = (3 * C_DIM * C_DIM + 255) / 256;
    wsplit3_kernel<<<wb3, 256>>>(q_w, k_w, v_w, q_bn, k_bn, v_bn, wqkvh, wqkvl, offqkv);
    int wb = (C_DIM * C_DIM + 255) / 256;
    wsplit_kernel<<<wb, 256>>>(proj_w, proj_bn, proj_b, wph, wpl, offp, C_DIM, C_DIM, 0);
    int wb1 = (H_DIM * C_DIM + 255) / 256;
    wsplit_kernel<<<wb1, 256>>>(fc1_w, fc1_bn, fc1_b, w1h, w1l, off1, H_DIM, C_DIM, 0);
    wsplit_kernel<<<wb1, 256>>>(fc2_w, fc2_bn, fc2_b, w2h, w2l, off2, C_DIM, H_DIM, 0);
    xsplit_kernel<<<tgrid, tb32>>>(x, xh, xl);

    const int eptQ = BATCH * N_SP * QKV_M;
    const int eptC = BATCH * N_SP * C_DIM;
    const int eptH = BATCH * N_SP * H_DIM;

    // launch 6: the dominant GEMM (ncu capture target)
    gemm_hmma<<<dim3(7, QKV_M / 128, TB), 256, GSMEM>>>(xh, xl, wqkvh, wqkvl, offqkv, pre,
                                                        C_DIM, QKV_M, 2);
    lif_kernel<<<(eptQ / 2 + 255) / 256, 256>>>(pre, qkv, eptQ, 1.0f);

    attn_m_kernel<<<TB * NH, 256>>>(qkv, Mb);
    attn_o_lif_kernel<<<dim3(7, NH, BATCH), 128>>>(qkv, Mb, aspk);

    gemm_hmma<<<dim3(7, C_DIM / 128, TB), 256, GSMEM>>>(aspk, aspk, wph, wpl, offp, pre,
                                                        C_DIM, C_DIM, 1);
    lif_kernel<<<(eptC / 2 + 255) / 256, 256>>>(pre, pspk, eptC, 1.0f);

    x1_kernel<<<tgrid, tb32>>>(x, pspk, x1f, x1h, x1l);

    gemm_hmma<<<dim3(7, H_DIM / 128, TB), 256, GSMEM>>>(x1h, x1l, w1h, w1l, off1, pre,
                                                        C_DIM, H_DIM, 2);
    lif_kernel<<<(eptH / 2 + 255) / 256, 256>>>(pre, hspk, eptH, 1.0f);

    gemm_hmma<<<dim3(7, C_DIM / 128, TB), 256, GSMEM>>>(hspk, hspk, w2h, w2l, off2, pre,
                                                        H_DIM, C_DIM, 1);
    lif_kernel<<<(eptC / 2 + 255) / 256, 256>>>(pre, mspk, eptC, 1.0f);

    final_kernel<<<tgrid, tb32>>>(x1f, mspk, out);
}

// round 11
// speedup vs baseline: 1.0412x; 1.0412x over previous
#include <cuda_runtime.h>
#include <cuda_fp16.h>
#include <cstdint>
#include <cstddef>

#define T_STEPS 4
#define BATCH   8
#define C_DIM   384
#define H_DIM   1536
#define QKV_M   1152
#define N_SP    784
#define NH      8
#define HD      48
#define TB      32

// ---------------- scratch ----------------------------------------------------
__device__ __align__(256) float  g_pre [(size_t)TB*N_SP*H_DIM];
__device__ __align__(256) __half g_xh  [(size_t)TB*N_SP*C_DIM];
__device__ __align__(256) __half g_xl  [(size_t)TB*N_SP*C_DIM];
__device__ __align__(256) __half g_wqkvh[(size_t)QKV_M*C_DIM];
__device__ __align__(256) __half g_wqkvl[(size_t)QKV_M*C_DIM];
__device__ __align__(256) __half g_wph[(size_t)C_DIM*C_DIM];
__device__ __align__(256) __half g_wpl[(size_t)C_DIM*C_DIM];
__device__ __align__(256) __half g_w1h[(size_t)H_DIM*C_DIM];
__device__ __align__(256) __half g_w1l[(size_t)H_DIM*C_DIM];
__device__ __align__(256) __half g_w2h[(size_t)C_DIM*H_DIM];
__device__ __align__(256) __half g_w2l[(size_t)C_DIM*H_DIM];
__device__ __align__(256) float  g_offqkv[QKV_M];
__device__ __align__(256) float  g_offp[C_DIM];
__device__ __align__(256) float  g_off1[H_DIM];
__device__ __align__(256) float  g_off2[C_DIM];
__device__ __align__(256) __half g_qkv [(size_t)TB*N_SP*QKV_M];
__device__ __align__(256) float  g_M   [(size_t)TB*NH*HD*HD];
__device__ __align__(256) __half g_aspk[(size_t)TB*N_SP*C_DIM];
__device__ __align__(256) __half g_pspk[(size_t)TB*N_SP*C_DIM];
__device__ __align__(256) __half g_x1h [(size_t)TB*N_SP*C_DIM];
__device__ __align__(256) __half g_x1l [(size_t)TB*N_SP*C_DIM];
__device__ __align__(256) float  g_x1f [(size_t)TB*C_DIM*N_SP];
__device__ __align__(256) __half g_hspk[(size_t)TB*N_SP*H_DIM];
__device__ __align__(256) __half g_mspk[(size_t)TB*N_SP*C_DIM];

// ---------------- helpers ----------------------------------------------------
__device__ __forceinline__ uint32_t smem_u32(const void* p) {
    uint32_t a;
    asm("{ .reg .u64 t; cvta.to.shared.u64 t, %1; cvt.u32.u64 %0, t; }" : "=r"(a) : "l"(p));
    return a;
}
__device__ __forceinline__ void ldsm4(uint32_t* r, uint32_t addr) {
    asm volatile("ldmatrix.sync.aligned.m8n8.x4.shared.b16 {%0,%1,%2,%3}, [%4];"
        : "=r"(r[0]), "=r"(r[1]), "=r"(r[2]), "=r"(r[3]) : "r"(addr));
}
__device__ __forceinline__ void mma16816(float* d, const uint32_t* a, const uint32_t* b) {
    asm volatile("mma.sync.aligned.m16n8k16.row.col.f32.f16.f16.f32 "
        "{%0,%1,%2,%3}, {%4,%5,%6,%7}, {%8,%9}, {%0,%1,%2,%3};"
        : "+f"(d[0]), "+f"(d[1]), "+f"(d[2]), "+f"(d[3])
        : "r"(a[0]), "r"(a[1]), "r"(a[2]), "r"(a[3]), "r"(b[0]), "r"(b[1]));
}
__device__ __forceinline__ void cp16(uint32_t dst, const void* src, int szz) {
    asm volatile("cp.async.ca.shared.global [%0], [%1], 16, %2;"
                 :: "r"(dst), "l"(src), "r"(szz));
}
__device__ __forceinline__ void cp_commit() {
    asm volatile("cp.async.commit_group;" ::: "memory");
}
template<int N> __device__ __forceinline__ void cp_wait() {
    asm volatile("cp.async.wait_group %0;" :: "n"(N) : "memory");
}

// ---------------- weight fold + split ---------------------------------------
__device__ __forceinline__ void wsplit_one(const float* w, const float* bnp,
                                           const float* bias, __half* wh, __half* wl,
                                           float* off, int O, int C, int dstRow, int idx) {
    int o = idx / C, c = idx - o * C;
    float inv = bnp[o] / sqrtf(bnp[3*O + o] + 1e-5f);
    float wv = w[idx] * inv;
    __half h = __float2half_rn(wv);
    size_t d = (size_t)(dstRow + o) * C + c;
    wh[d] = h;
    wl[d] = __float2half_rn(wv - __half2float(h));
    if (c == 0) {
        float bb = bias ? bias[o] : 0.0f;
        off[dstRow + o] = (bb - bnp[2*O + o]) * inv + bnp[O + o];
    }
}

__global__ void wsplit_kernel(const float* __restrict__ w, const float* __restrict__ bnp,
                              const float* __restrict__ bias,
                              __half* __restrict__ wh, __half* __restrict__ wl,
                              float* __restrict__ off, int O, int C, int dstRow) {
    int idx = blockIdx.x * blockDim.x + threadIdx.x;
    if (idx >= O * C) return;
    wsplit_one(w, bnp, bias, wh, wl, off, O, C, dstRow, idx);
}

__global__ void wsplit3_kernel(const float* __restrict__ qw, const float* __restrict__ kw,
                               const float* __restrict__ vw, const float* __restrict__ qbn,
                               const float* __restrict__ kbn, const float* __restrict__ vbn,
                               __half* __restrict__ wh, __half* __restrict__ wl,
                               float* __restrict__ off) {
    const int per = C_DIM * C_DIM;
    int gidx = blockIdx.x * blockDim.x + threadIdx.x;
    if (gidx >= 3 * per) return;
    int wi = gidx / per, idx = gidx - wi * per;
    const float* w   = (wi == 0) ? qw  : (wi == 1) ? kw  : vw;
    const float* bnp = (wi == 0) ? qbn : (wi == 1) ? kbn : vbn;
    wsplit_one(w, bnp, nullptr, wh, wl, off, C_DIM, C_DIM, wi * C_DIM, idx);
}

// ---------------- x: [tb,C,N] f32 -> [tb,n,C] f16 h/l ------------------------
__global__ void xsplit_kernel(const float* __restrict__ x,
                              __half* __restrict__ xh, __half* __restrict__ xl) {
    __shared__ float t[32][33];
    int tb = blockIdx.z, c0 = blockIdx.x * 32, n0 = blockIdx.y * 32;
    int tx = threadIdx.x, ty = threadIdx.y;
    #pragma unroll
    for (int i = 0; i < 4; i++) {
        int cl = ty + i * 8, n = n0 + tx;
        t[cl][tx] = (n < N_SP) ? x[((size_t)tb * C_DIM + c0 + cl) * N_SP + n] : 0.0f;
    }
    __syncthreads();
    #pragma unroll
    for (int i = 0; i < 4; i++) {
        int nl = ty + i * 8, n = n0 + nl;
        if (n < N_SP) {
            float v = t[tx][nl];
            __half h = __float2half_rn(v);
            size_t d = ((size_t)tb * N_SP + n) * C_DIM + c0 + tx;
            xh[d] = h;
            xl[d] = __float2half_rn(v - __half2float(h));
        }
    }
}

// ---------------- pipelined HMMA GEMM (KC=32, 2-stage, 1 sync/chunk) ---------
// pre[tb,n,c] = sum_k Act[tb,n,k]*W[c,k] + off[c]
#define STRD 40
#define TILEB (128*STRD*2)        // 10240 B
#define STAGEB (4*TILEB)          // 40960
#define GSMEM (2*STAGEB)          // 81920
__global__ __launch_bounds__(256, 2) void gemm_hmma(
    const __half* __restrict__ A0, const __half* __restrict__ A1,
    const __half* __restrict__ W0, const __half* __restrict__ W1,
    const float* __restrict__ off, float* __restrict__ pre,
    int K, int Mtot, int nsA)
{
    extern __shared__ char smraw[];
    const int tb = blockIdx.z;
    const int n0 = blockIdx.x * 128;
    const int m0 = blockIdx.y * 128;
    const int tid = threadIdx.x;
    const int lane = tid & 31, warp = tid >> 5;
    const int wn = (warp >> 2) * 64;
    const int wc = (warp & 3) * 32;
    const uint32_t smb = smem_u32(smraw);
    const __half* Wops[2] = {W0, W1};

    const int lrow = tid >> 1, lp = (tid & 1) * 16;
    const int nA = n0 + lrow;
    const int nAc = (nA < N_SP) ? nA : (N_SP - 1);
    const int aSz = (nA < N_SP) ? 16 : 0;
    const __half* aptr[2] = {
        A0 + ((size_t)tb * N_SP + nAc) * K,
        A1 + ((size_t)tb * N_SP + nAc) * K };

    float acc[4][4][4];
    #pragma unroll
    for (int mi = 0; mi < 4; mi++)
        #pragma unroll
        for (int cj = 0; cj < 4; cj++)
            #pragma unroll
            for (int r = 0; r < 4; r++) acc[mi][cj][r] = 0.0f;

    const int a_row = lane & 15;
    const int a_col = ((lane >> 4) & 1) * 8;
    const int w_row = ((lane >> 4) & 1) * 8 + (lane & 7);
    const int w_col = ((lane >> 3) & 1) * 8;

    #define LOADST(ST, K0)                                                          \
    {                                                                               \
        _Pragma("unroll")                                                           \
        for (int s = 0; s < 2; s++) {                                               \
            if (s < nsA) {                                                          \
                const __half* src = aptr[s] + (K0) + lp;                            \
                uint32_t dst = smb + (ST) * STAGEB + s * TILEB + (lrow * STRD + lp) * 2; \
                cp16(dst, src, aSz);                                                \
                cp16(dst + 16, src + 8, aSz);                                       \
            }                                                                       \
            const __half* wsrc = Wops[s] + (size_t)(m0 + lrow) * K + (K0) + lp;     \
            uint32_t wdst = smb + (ST) * STAGEB + (2 + s) * TILEB + (lrow * STRD + lp) * 2; \
            cp16(wdst, wsrc, 16);                                                   \
            cp16(wdst + 16, wsrc + 8, 16);                                          \
        }                                                                           \
        cp_commit();                                                                \
    }

    const int nch = K / 32;
    LOADST(0, 0)

    for (int ch = 0; ch < nch; ch++) {
        const int st = ch & 1;
        // wait for current stage's loads, barrier (also ensures all warps are
        // done COMPUTING stage st^1 from last iteration), then prefetch into
        // st^1 and compute st. Canonical single-barrier multistage ordering.
        cp_wait<0>();
        __syncthreads();
        if (ch + 1 < nch) {
            LOADST(st ^ 1, (ch + 1) * 32)
        }

        #pragma unroll
        for (int ks = 0; ks < 2; ks++) {
            uint32_t wf[2][8];
            #pragma unroll
            for (int s = 0; s < 2; s++)
                #pragma unroll
                for (int hb = 0; hb < 2; hb++) {
                    uint32_t ad = smb + st * STAGEB + (2 + s) * TILEB
                        + ((wc + hb * 16 + w_row) * STRD + ks * 16 + w_col) * 2;
                    ldsm4(&wf[s][hb * 4], ad);
                }
            #pragma unroll
            for (int mi = 0; mi < 4; mi++) {
                uint32_t af[2][4];
                #pragma unroll
                for (int s = 0; s < 2; s++)
                    if (s < nsA) {
                        uint32_t ad = smb + st * STAGEB + s * TILEB
                            + ((wn + mi * 16 + a_row) * STRD + ks * 16 + a_col) * 2;
                        ldsm4(af[s], ad);
                    }
                #pragma unroll
                for (int cj = 0; cj < 4; cj++) {
                    mma16816(acc[mi][cj], af[0], &wf[0][cj * 2]);     // Ah*Wh
                    mma16816(acc[mi][cj], af[0], &wf[1][cj * 2]);     // Ah*Wl
                    if (nsA == 2)
                        mma16816(acc[mi][cj], af[1], &wf[0][cj * 2]); // Al*Wh
                }
            }
        }
    }
    #undef LOADST

    // epilogue: add off, store fp32 preact
    #pragma unroll
    for (int mi = 0; mi < 4; mi++) {
        int rA = n0 + wn + mi * 16 + (lane >> 2);
        int rB = rA + 8;
        #pragma unroll
        for (int cj = 0; cj < 4; cj++) {
            int c = m0 + wc + cj * 8 + 2 * (lane & 3);
            float o0 = off[c], o1 = off[c + 1];
            if (rA < N_SP) {
                float2 v = {acc[mi][cj][0] + o0, acc[mi][cj][1] + o1};
                *(float2*)(pre + ((size_t)tb * N_SP + rA) * Mtot + c) = v;
            }
            if (rB < N_SP) {
                float2 v = {acc[mi][cj][2] + o0, acc[mi][cj][3] + o1};
                *(float2*)(pre + ((size_t)tb * N_SP + rB) * Mtot + c) = v;
            }
        }
    }
}

// ---------------- LIF over T=4 on [tb,n,M] layout (x2 vectorized) ------------
__global__ void lif_kernel(const float* __restrict__ pre, __half* __restrict__ spk,
                           int ept, float vth)
{
    int i = (blockIdx.x * blockDim.x + threadIdx.x) * 2;
    if (i >= ept) return;
    float v0 = 0.0f, v1 = 0.0f;
    #pragma unroll
    for (int t = 0; t < T_STEPS; t++) {
        float2 x = *(const float2*)(pre + i + (size_t)t * ept);
        v0 = __fadd_rn(v0, __fmul_rn(__fsub_rn(x.x, v0), 0.5f));
        v1 = __fadd_rn(v1, __fmul_rn(__fsub_rn(x.y, v1), 0.5f));
        float s0 = (v0 >= vth) ? 1.0f : 0.0f;
        float s1 = (v1 >= vth) ? 1.0f : 0.0f;
        __half2 sp = __floats2half2_rn(s0, s1);
        *(__half2*)(spk + i + (size_t)t * ept) = sp;
        if (s0 != 0.0f) v0 = 0.0f;
        if (s1 != 0.0f) v1 = 0.0f;
    }
}

// ---------------- attention: M = K^T V (exact ints) --------------------------
__global__ __launch_bounds__(256) void attn_m_kernel(const __half* __restrict__ qkv,
                                                     float* __restrict__ Mout) {
    __shared__ float Ks[64][HD];
    __shared__ float Vs[64][HD];
    const int zz = blockIdx.x, h = zz & 7, tb = zz >> 3;
    const int tid = threadIdx.x;
    const __half* Kb = qkv + (size_t)tb * N_SP * QKV_M + C_DIM + h * HD;
    const __half* Vb = qkv + (size_t)tb * N_SP * QKV_M + 2 * C_DIM + h * HD;
    float acc[9]; int di[9], ei[9];
    #pragma unroll
    for (int i = 0; i < 9; i++) {
        acc[i] = 0.0f;
        int p = tid + i * 256; di[i] = p / HD; ei[i] = p % HD;
    }
    for (int nn0 = 0; nn0 < N_SP; nn0 += 64) {
        for (int l = tid; l < 64 * HD; l += 256) {
            int r = l / HD, cc = l % HD, n = nn0 + r;
            float kv = 0.0f, vv = 0.0f;
            if (n < N_SP) {
                kv = __half2float(Kb[(size_t)n * QKV_M + cc]);
                vv = __half2float(Vb[(size_t)n * QKV_M + cc]);
            }
            Ks[r][cc] = kv; Vs[r][cc] = vv;
        }
        __syncthreads();
        #pragma unroll
        for (int i = 0; i < 9; i++) {
            float s = acc[i];
            #pragma unroll
            for (int nn = 0; nn < 64; nn++) s += Ks[nn][di[i]] * Vs[nn][ei[i]];
            acc[i] = s;
        }
        __syncthreads();
    }
    #pragma unroll
    for (int i = 0; i < 9; i++) Mout[(size_t)zz * (HD * HD) + tid + i * 256] = acc[i];
}

// ---------------- O = Q*M*0.25 + fused attn-LIF (vth=0.5) --------------------
__global__ __launch_bounds__(128) void attn_o_lif_kernel(const __half* __restrict__ qkv,
                                                         const float* __restrict__ Mbuf,
                                                         __half* __restrict__ aspk) {
    __shared__ float Ms[HD * HD];
    const int nt = blockIdx.x, h = blockIdx.y, b = blockIdx.z;
    const int tid = threadIdx.x;
    const int n = nt * 128 + tid;
    float v[HD];
    #pragma unroll
    for (int e = 0; e < HD; e++) v[e] = 0.0f;
    for (int t = 0; t < 4; t++) {
        int tb = t * BATCH + b;
        for (int l = tid; l < HD * HD; l += 128)
            Ms[l] = Mbuf[((size_t)tb * NH + h) * (HD * HD) + l];
        __syncthreads();
        if (n < N_SP) {
            const __half* Qp = qkv + ((size_t)tb * N_SP + n) * QKV_M + h * HD;
            float q[HD];
            #pragma unroll
            for (int d = 0; d < HD; d++) q[d] = __half2float(Qp[d]);
            __half* Op = aspk + ((size_t)tb * N_SP + n) * C_DIM + h * HD;
            #pragma unroll 4
            for (int e = 0; e < HD; e++) {
                float s = 0.0f;
                #pragma unroll
                for (int d = 0; d < HD; d++) s += q[d] * Ms[d * HD + e];
                float x = s * 0.25f;
                float ve = v[e];
                ve = __fadd_rn(ve, __fmul_rn(__fsub_rn(x, ve), 0.5f));
                float sp = (ve >= 0.5f) ? 1.0f : 0.0f;
                Op[e] = __float2half_rn(sp);
                v[e] = (sp != 0.0f) ? 0.0f : ve;
            }
        }
        __syncthreads();
    }
}

// ---------------- x1 = x + proj_spk -----------------------------------------
__global__ void x1_kernel(const float* __restrict__ x, const __half* __restrict__ pspk,
                          float* __restrict__ x1f,
                          __half* __restrict__ x1h, __half* __restrict__ x1l) {
    __shared__ float s[32][33];
    int tb = blockIdx.z, c0 = blockIdx.x * 32, n0 = blockIdx.y * 32;
    int tx = threadIdx.x, ty = threadIdx.y;
    #pragma unroll
    for (int i = 0; i < 4; i++) {
        int nl = ty + i * 8, n = n0 + nl;
        s[nl][tx] = (n < N_SP)
            ? __half2float(pspk[((size_t)tb * N_SP + n) * C_DIM + c0 + tx]) : 0.0f;
    }
    __syncthreads();
    #pragma unroll
    for (int i = 0; i < 4; i++) {
        int cl = ty + i * 8, n = n0 + tx;
        if (n < N_SP) {
            size_t xi = ((size_t)tb * C_DIM + c0 + cl) * N_SP + n;
            float val = x[xi] + s[tx][cl];
            x1f[xi] = val;
            s[tx][cl] = val;
        }
    }
    __syncthreads();
    #pragma unroll
    for (int i = 0; i < 4; i++) {
        int nl = ty + i * 8, n = n0 + nl;
        if (n < N_SP) {
            float val = s[nl][tx];
            __half h = __float2half_rn(val);
            size_t d = ((size_t)tb * N_SP + n) * C_DIM + c0 + tx;
            x1h[d] = h;
            x1l[d] = __float2half_rn(val - __half2float(h));
        }
    }
}

// ---------------- out = x1f + mspk^T ----------------------------------------
__global__ void final_kernel(const float* __restrict__ x1f, const __half* __restrict__ mspk,
                             float* __restrict__ out) {
    __shared__ float s[32][33];
    int tb = blockIdx.z, c0 = blockIdx.x * 32, n0 = blockIdx.y * 32;
    int tx = threadIdx.x, ty = threadIdx.y;
    #pragma unroll
    for (int i = 0; i < 4; i++) {
        int nl = ty + i * 8, n = n0 + nl;
        s[nl][tx] = (n < N_SP)
            ? __half2float(mspk[((size_t)tb * N_SP + n) * C_DIM + c0 + tx]) : 0.0f;
    }
    __syncthreads();
    #pragma unroll
    for (int i = 0; i < 4; i++) {
        int cl = ty + i * 8, n = n0 + tx;
        if (n < N_SP) {
            size_t xi = ((size_t)tb * C_DIM + c0 + cl) * N_SP + n;
            out[xi] = x1f[xi] + s[tx][cl];
        }
    }
}

// ---------------------------------------------------------------------------
extern "C" void kernel_launch(void* const* d_in, const int* in_sizes, int n_in,
                              void* d_out, int out_size) {
    const float* x      = (const float*)d_in[0];
    const float* q_w    = (const float*)d_in[1];
    const float* k_w    = (const float*)d_in[2];
    const float* v_w    = (const float*)d_in[3];
    const float* q_bn   = (const float*)d_in[4];
    const float* k_bn   = (const float*)d_in[5];
    const float* v_bn   = (const float*)d_in[6];
    const float* proj_w = (const float*)d_in[7];
    const float* proj_b = (const float*)d_in[8];
    const float* proj_bn= (const float*)d_in[9];
    const float* fc1_w  = (const float*)d_in[10];
    const float* fc1_b  = (const float*)d_in[11];
    const float* fc1_bn = (const float*)d_in[12];
    const float* fc2_w  = (const float*)d_in[13];
    const float* fc2_b  = (const float*)d_in[14];
    const float* fc2_bn = (const float*)d_in[15];
    float* out = (float*)d_out;

    cudaFuncSetAttribute(gemm_hmma, cudaFuncAttributeMaxDynamicSharedMemorySize, GSMEM);

    __half *xh, *xl, *wqkvh, *wqkvl, *wph, *wpl, *w1h, *w1l, *w2h, *w2l;
    __half *qkv, *aspk, *pspk, *x1h, *x1l, *hspk, *mspk;
    float *offqkv, *offp, *off1, *off2, *Mb, *x1f, *pre;
    cudaGetSymbolAddress((void**)&pre, g_pre);
    cudaGetSymbolAddress((void**)&xh, g_xh);       cudaGetSymbolAddress((void**)&xl, g_xl);
    cudaGetSymbolAddress((void**)&wqkvh, g_wqkvh); cudaGetSymbolAddress((void**)&wqkvl, g_wqkvl);
    cudaGetSymbolAddress((void**)&wph, g_wph);     cudaGetSymbolAddress((void**)&wpl, g_wpl);
    cudaGetSymbolAddress((void**)&w1h, g_w1h);     cudaGetSymbolAddress((void**)&w1l, g_w1l);
    cudaGetSymbolAddress((void**)&w2h, g_w2h);     cudaGetSymbolAddress((void**)&w2l, g_w2l);
    cudaGetSymbolAddress((void**)&offqkv, g_offqkv); cudaGetSymbolAddress((void**)&offp, g_offp);
    cudaGetSymbolAddress((void**)&off1, g_off1);   cudaGetSymbolAddress((void**)&off2, g_off2);
    cudaGetSymbolAddress((void**)&qkv, g_qkv);     cudaGetSymbolAddress((void**)&Mb, g_M);
    cudaGetSymbolAddress((void**)&aspk, g_aspk);   cudaGetSymbolAddress((void**)&pspk, g_pspk);
    cudaGetSymbolAddress((void**)&x1h, g_x1h);     cudaGetSymbolAddress((void**)&x1l, g_x1l);
    cudaGetSymbolAddress((void**)&x1f, g_x1f);
    cudaGetSymbolAddress((void**)&hspk, g_hspk);   cudaGetSymbolAddress((void**)&mspk, g_mspk);

    dim3 tb32(32, 8);
    dim3 tgrid(C_DIM / 32, (N_SP + 31) / 32, TB);

    int wb3 = (3 * C_DIM * C_DIM + 255) / 256;
    wsplit3_kernel<<<wb3, 256>>>(q_w, k_w, v_w, q_bn, k_bn, v_bn, wqkvh, wqkvl, offqkv);
    int wb = (C_DIM * C_DIM + 255) / 256;
    wsplit_kernel<<<wb, 256>>>(proj_w, proj_bn, proj_b, wph, wpl, offp, C_DIM, C_DIM, 0);
    int wb1 = (H_DIM * C_DIM + 255) / 256;
    wsplit_kernel<<<wb1, 256>>>(fc1_w, fc1_bn, fc1_b, w1h, w1l, off1, H_DIM, C_DIM, 0);
    wsplit_kernel<<<wb1, 256>>>(fc2_w, fc2_bn, fc2_b, w2h, w2l, off2, C_DIM, H_DIM, 0);
    xsplit_kernel<<<tgrid, tb32>>>(x, xh, xl);

    const int eptQ = BATCH * N_SP * QKV_M;
    const int eptC = BATCH * N_SP * C_DIM;
    const int eptH = BATCH * N_SP * H_DIM;

    gemm_hmma<<<dim3(7, QKV_M / 128, TB), 256, GSMEM>>>(xh, xl, wqkvh, wqkvl, offqkv, pre,
                                                        C_DIM, QKV_M, 2);
    lif_kernel<<<(eptQ / 2 + 255) / 256, 256>>>(pre, qkv, eptQ, 1.0f);

    attn_m_kernel<<<TB * NH, 256>>>(qkv, Mb);
    attn_o_lif_kernel<<<dim3(7, NH, BATCH), 128>>>(qkv, Mb, aspk);

    gemm_hmma<<<dim3(7, C_DIM / 128, TB), 256, GSMEM>>>(aspk, aspk, wph, wpl, offp, pre,
                                                        C_DIM, C_DIM, 1);
    lif_kernel<<<(eptC / 2 + 255) / 256, 256>>>(pre, pspk, eptC, 1.0f);

    x1_kernel<<<tgrid, tb32>>>(x, pspk, x1f, x1h, x1l);

    gemm_hmma<<<dim3(7, H_DIM / 128, TB), 256, GSMEM>>>(x1h, x1l, w1h, w1l, off1, pre,
                                                        C_DIM, H_DIM, 2);
    lif_kernel<<<(eptH / 2 + 255) / 256, 256>>>(pre, hspk, eptH, 1.0f);

    gemm_hmma<<<dim3(7, C_DIM / 128, TB), 256, GSMEM>>>(hspk, hspk, w2h, w2l, off2, pre,
                                                        H_DIM, C_DIM, 1);
    lif_kernel<<<(eptC / 2 + 255) / 256, 256>>>(pre, mspk, eptC, 1.0f);

    final_kernel<<<tgrid, tb32>>>(x1f, mspk, out);
}

// round 12
// speedup vs baseline: 1.1380x; 1.0930x over previous
#include <cuda_runtime.h>
#include <cuda_fp16.h>
#include <cstdint>
#include <cstddef>

#define T_STEPS 4
#define BATCH   8
#define C_DIM   384
#define H_DIM   1536
#define QKV_M   1152
#define N_SP    784
#define NH      8
#define HD      48
#define TB      32
#define NROWS   (TB*N_SP)          // 25088 = 196*128, flat (tb,n) rows
#define NTILES  (NROWS/128)        // 196

// ---------------- scratch ----------------------------------------------------
__device__ __align__(256) float  g_pre [(size_t)TB*N_SP*H_DIM];
__device__ __align__(256) __half g_xh  [(size_t)TB*N_SP*C_DIM];
__device__ __align__(256) __half g_xl  [(size_t)TB*N_SP*C_DIM];
__device__ __align__(256) __half g_wqkvh[(size_t)QKV_M*C_DIM];
__device__ __align__(256) __half g_wqkvl[(size_t)QKV_M*C_DIM];
__device__ __align__(256) __half g_wph[(size_t)C_DIM*C_DIM];
__device__ __align__(256) __half g_wpl[(size_t)C_DIM*C_DIM];
__device__ __align__(256) __half g_w1h[(size_t)H_DIM*C_DIM];
__device__ __align__(256) __half g_w1l[(size_t)H_DIM*C_DIM];
__device__ __align__(256) __half g_w2h[(size_t)C_DIM*H_DIM];
__device__ __align__(256) __half g_w2l[(size_t)C_DIM*H_DIM];
__device__ __align__(256) float  g_offqkv[QKV_M];
__device__ __align__(256) float  g_offp[C_DIM];
__device__ __align__(256) float  g_off1[H_DIM];
__device__ __align__(256) float  g_off2[C_DIM];
__device__ __align__(256) __half g_qkv [(size_t)TB*N_SP*QKV_M];
__device__ __align__(256) float  g_M   [(size_t)TB*NH*HD*HD];
__device__ __align__(256) __half g_aspk[(size_t)TB*N_SP*C_DIM];
__device__ __align__(256) __half g_pspk[(size_t)TB*N_SP*C_DIM];
__device__ __align__(256) __half g_x1h [(size_t)TB*N_SP*C_DIM];
__device__ __align__(256) __half g_x1l [(size_t)TB*N_SP*C_DIM];
__device__ __align__(256) float  g_x1f [(size_t)TB*C_DIM*N_SP];
__device__ __align__(256) __half g_hspk[(size_t)TB*N_SP*H_DIM];
__device__ __align__(256) __half g_mspk[(size_t)TB*N_SP*C_DIM];

// ---------------- helpers ----------------------------------------------------
__device__ __forceinline__ uint32_t smem_u32(const void* p) {
    uint32_t a;
    asm("{ .reg .u64 t; cvta.to.shared.u64 t, %1; cvt.u32.u64 %0, t; }" : "=r"(a) : "l"(p));
    return a;
}
__device__ __forceinline__ void ldsm4(uint32_t* r, uint32_t addr) {
    asm volatile("ldmatrix.sync.aligned.m8n8.x4.shared.b16 {%0,%1,%2,%3}, [%4];"
        : "=r"(r[0]), "=r"(r[1]), "=r"(r[2]), "=r"(r[3]) : "r"(addr));
}
__device__ __forceinline__ void mma16816(float* d, const uint32_t* a, const uint32_t* b) {
    asm volatile("mma.sync.aligned.m16n8k16.row.col.f32.f16.f16.f32 "
        "{%0,%1,%2,%3}, {%4,%5,%6,%7}, {%8,%9}, {%0,%1,%2,%3};"
        : "+f"(d[0]), "+f"(d[1]), "+f"(d[2]), "+f"(d[3])
        : "r"(a[0]), "r"(a[1]), "r"(a[2]), "r"(a[3]), "r"(b[0]), "r"(b[1]));
}
__device__ __forceinline__ void cp16(uint32_t dst, const void* src) {
    asm volatile("cp.async.ca.shared.global [%0], [%1], 16;"
                 :: "r"(dst), "l"(src));
}
__device__ __forceinline__ void cp_commit() {
    asm volatile("cp.async.commit_group;" ::: "memory");
}
template<int N> __device__ __forceinline__ void cp_wait() {
    asm volatile("cp.async.wait_group %0;" :: "n"(N) : "memory");
}

// ---------------- weight fold + split ---------------------------------------
__device__ __forceinline__ void wsplit_one(const float* w, const float* bnp,
                                           const float* bias, __half* wh, __half* wl,
                                           float* off, int O, int C, int dstRow, int idx) {
    int o = idx / C, c = idx - o * C;
    float inv = bnp[o] / sqrtf(bnp[3*O + o] + 1e-5f);
    float wv = w[idx] * inv;
    __half h = __float2half_rn(wv);
    size_t d = (size_t)(dstRow + o) * C + c;
    wh[d] = h;
    wl[d] = __float2half_rn(wv - __half2float(h));
    if (c == 0) {
        float bb = bias ? bias[o] : 0.0f;
        off[dstRow + o] = (bb - bnp[2*O + o]) * inv + bnp[O + o];
    }
}

__global__ void wsplit_kernel(const float* __restrict__ w, const float* __restrict__ bnp,
                              const float* __restrict__ bias,
                              __half* __restrict__ wh, __half* __restrict__ wl,
                              float* __restrict__ off, int O, int C, int dstRow) {
    int idx = blockIdx.x * blockDim.x + threadIdx.x;
    if (idx >= O * C) return;
    wsplit_one(w, bnp, bias, wh, wl, off, O, C, dstRow, idx);
}

__global__ void wsplit3_kernel(const float* __restrict__ qw, const float* __restrict__ kw,
                               const float* __restrict__ vw, const float* __restrict__ qbn,
                               const float* __restrict__ kbn, const float* __restrict__ vbn,
                               __half* __restrict__ wh, __half* __restrict__ wl,
                               float* __restrict__ off) {
    const int per = C_DIM * C_DIM;
    int gidx = blockIdx.x * blockDim.x + threadIdx.x;
    if (gidx >= 3 * per) return;
    int wi = gidx / per, idx = gidx - wi * per;
    const float* w   = (wi == 0) ? qw  : (wi == 1) ? kw  : vw;
    const float* bnp = (wi == 0) ? qbn : (wi == 1) ? kbn : vbn;
    wsplit_one(w, bnp, nullptr, wh, wl, off, C_DIM, C_DIM, wi * C_DIM, idx);
}

// ---------------- x: [tb,C,N] f32 -> [tb,n,C] f16 h/l ------------------------
__global__ void xsplit_kernel(const float* __restrict__ x,
                              __half* __restrict__ xh, __half* __restrict__ xl) {
    __shared__ float t[32][33];
    int tb = blockIdx.z, c0 = blockIdx.x * 32, n0 = blockIdx.y * 32;
    int tx = threadIdx.x, ty = threadIdx.y;
    #pragma unroll
    for (int i = 0; i < 4; i++) {
        int cl = ty + i * 8, n = n0 + tx;
        t[cl][tx] = (n < N_SP) ? x[((size_t)tb * C_DIM + c0 + cl) * N_SP + n] : 0.0f;
    }
    __syncthreads();
    #pragma unroll
    for (int i = 0; i < 4; i++) {
        int nl = ty + i * 8, n = n0 + nl;
        if (n < N_SP) {
            float v = t[tx][nl];
            __half h = __float2half_rn(v);
            size_t d = ((size_t)tb * N_SP + n) * C_DIM + c0 + tx;
            xh[d] = h;
            xl[d] = __float2half_rn(v - __half2float(h));
        }
    }
}

// ---------------- pipelined HMMA GEMM (flat rows, KC=32, 2-stage, 1 sync) ----
// pre[r,c] = sum_k Act[r,k]*W[c,k] + off[c],  r in [0, NROWS)
#define STRD 40
#define TILEB (128*STRD*2)        // 10240 B
#define STAGEB (4*TILEB)          // 40960
#define GSMEM (2*STAGEB)          // 81920
__global__ __launch_bounds__(256, 2) void gemm_hmma(
    const __half* __restrict__ A0, const __half* __restrict__ A1,
    const __half* __restrict__ W0, const __half* __restrict__ W1,
    const float* __restrict__ off, float* __restrict__ pre,
    int K, int Mtot, int nsA)
{
    extern __shared__ char smraw[];
    const int r0 = blockIdx.x * 128;        // flat (tb,n) row base — always full
    const int m0 = blockIdx.y * 128;
    const int tid = threadIdx.x;
    const int lane = tid & 31, warp = tid >> 5;
    const int wn = (warp >> 2) * 64;
    const int wc = (warp & 3) * 32;
    const uint32_t smb = smem_u32(smraw);
    const __half* Wops[2] = {W0, W1};

    const int lrow = tid >> 1, lp = (tid & 1) * 16;
    const __half* aptr[2] = {
        A0 + (size_t)(r0 + lrow) * K,
        A1 + (size_t)(r0 + lrow) * K };

    float acc[4][4][4];
    #pragma unroll
    for (int mi = 0; mi < 4; mi++)
        #pragma unroll
        for (int cj = 0; cj < 4; cj++)
            #pragma unroll
            for (int r = 0; r < 4; r++) acc[mi][cj][r] = 0.0f;

    const int a_row = lane & 15;
    const int a_col = ((lane >> 4) & 1) * 8;
    const int w_row = ((lane >> 4) & 1) * 8 + (lane & 7);
    const int w_col = ((lane >> 3) & 1) * 8;

    #define LOADST(ST, K0)                                                          \
    {                                                                               \
        _Pragma("unroll")                                                           \
        for (int s = 0; s < 2; s++) {                                               \
            if (s < nsA) {                                                          \
                const __half* src = aptr[s] + (K0) + lp;                            \
                uint32_t dst = smb + (ST) * STAGEB + s * TILEB + (lrow * STRD + lp) * 2; \
                cp16(dst, src);                                                     \
                cp16(dst + 16, src + 8);                                            \
            }                                                                       \
            const __half* wsrc = Wops[s] + (size_t)(m0 + lrow) * K + (K0) + lp;     \
            uint32_t wdst = smb + (ST) * STAGEB + (2 + s) * TILEB + (lrow * STRD + lp) * 2; \
            cp16(wdst, wsrc);                                                       \
            cp16(wdst + 16, wsrc + 8);                                              \
        }                                                                           \
        cp_commit();                                                                \
    }

    const int nch = K / 32;
    LOADST(0, 0)

    for (int ch = 0; ch < nch; ch++) {
        const int st = ch & 1;
        cp_wait<0>();
        __syncthreads();
        if (ch + 1 < nch) {
            LOADST(st ^ 1, (ch + 1) * 32)
        }

        #pragma unroll
        for (int ks = 0; ks < 2; ks++) {
            uint32_t wf[2][8];
            #pragma unroll
            for (int s = 0; s < 2; s++)
                #pragma unroll
                for (int hb = 0; hb < 2; hb++) {
                    uint32_t ad = smb + st * STAGEB + (2 + s) * TILEB
                        + ((wc + hb * 16 + w_row) * STRD + ks * 16 + w_col) * 2;
                    ldsm4(&wf[s][hb * 4], ad);
                }
            #pragma unroll
            for (int mi = 0; mi < 4; mi++) {
                uint32_t af[2][4];
                #pragma unroll
                for (int s = 0; s < 2; s++)
                    if (s < nsA) {
                        uint32_t ad = smb + st * STAGEB + s * TILEB
                            + ((wn + mi * 16 + a_row) * STRD + ks * 16 + a_col) * 2;
                        ldsm4(af[s], ad);
                    }
                #pragma unroll
                for (int cj = 0; cj < 4; cj++) {
                    mma16816(acc[mi][cj], af[0], &wf[0][cj * 2]);     // Ah*Wh
                    mma16816(acc[mi][cj], af[0], &wf[1][cj * 2]);     // Ah*Wl
                    if (nsA == 2)
                        mma16816(acc[mi][cj], af[1], &wf[0][cj * 2]); // Al*Wh
                }
            }
        }
    }
    #undef LOADST

    // epilogue: add off, store fp32 preact (no bounds — all rows valid)
    #pragma unroll
    for (int mi = 0; mi < 4; mi++) {
        int rA = r0 + wn + mi * 16 + (lane >> 2);
        int rB = rA + 8;
        #pragma unroll
        for (int cj = 0; cj < 4; cj++) {
            int c = m0 + wc + cj * 8 + 2 * (lane & 3);
            float o0 = off[c], o1 = off[c + 1];
            float2 v0 = {acc[mi][cj][0] + o0, acc[mi][cj][1] + o1};
            *(float2*)(pre + (size_t)rA * Mtot + c) = v0;
            float2 v1 = {acc[mi][cj][2] + o0, acc[mi][cj][3] + o1};
            *(float2*)(pre + (size_t)rB * Mtot + c) = v1;
        }
    }
}

// ---------------- LIF over T=4 on [tb,n,M] layout (x2 vectorized) ------------
__global__ void lif_kernel(const float* __restrict__ pre, __half* __restrict__ spk,
                           int ept, float vth)
{
    int i = (blockIdx.x * blockDim.x + threadIdx.x) * 2;
    if (i >= ept) return;
    float v0 = 0.0f, v1 = 0.0f;
    #pragma unroll
    for (int t = 0; t < T_STEPS; t++) {
        float2 x = *(const float2*)(pre + i + (size_t)t * ept);
        v0 = __fadd_rn(v0, __fmul_rn(__fsub_rn(x.x, v0), 0.5f));
        v1 = __fadd_rn(v1, __fmul_rn(__fsub_rn(x.y, v1), 0.5f));
        float s0 = (v0 >= vth) ? 1.0f : 0.0f;
        float s1 = (v1 >= vth) ? 1.0f : 0.0f;
        __half2 sp = __floats2half2_rn(s0, s1);
        *(__half2*)(spk + i + (size_t)t * ept) = sp;
        if (s0 != 0.0f) v0 = 0.0f;
        if (s1 != 0.0f) v1 = 0.0f;
    }
}

// ---------------- attention: M = K^T V (exact ints) --------------------------
__global__ __launch_bounds__(256) void attn_m_kernel(const __half* __restrict__ qkv,
                                                     float* __restrict__ Mout) {
    __shared__ float Ks[64][HD];
    __shared__ float Vs[64][HD];
    const int zz = blockIdx.x, h = zz & 7, tb = zz >> 3;
    const int tid = threadIdx.x;
    const __half* Kb = qkv + (size_t)tb * N_SP * QKV_M + C_DIM + h * HD;
    const __half* Vb = qkv + (size_t)tb * N_SP * QKV_M + 2 * C_DIM + h * HD;
    float acc[9]; int di[9], ei[9];
    #pragma unroll
    for (int i = 0; i < 9; i++) {
        acc[i] = 0.0f;
        int p = tid + i * 256; di[i] = p / HD; ei[i] = p % HD;
    }
    for (int nn0 = 0; nn0 < N_SP; nn0 += 64) {
        for (int l = tid; l < 64 * HD; l += 256) {
            int r = l / HD, cc = l % HD, n = nn0 + r;
            float kv = 0.0f, vv = 0.0f;
            if (n < N_SP) {
                kv = __half2float(Kb[(size_t)n * QKV_M + cc]);
                vv = __half2float(Vb[(size_t)n * QKV_M + cc]);
            }
            Ks[r][cc] = kv; Vs[r][cc] = vv;
        }
        __syncthreads();
        #pragma unroll
        for (int i = 0; i < 9; i++) {
            float s = acc[i];
            #pragma unroll
            for (int nn = 0; nn < 64; nn++) s += Ks[nn][di[i]] * Vs[nn][ei[i]];
            acc[i] = s;
        }
        __syncthreads();
    }
    #pragma unroll
    for (int i = 0; i < 9; i++) Mout[(size_t)zz * (HD * HD) + tid + i * 256] = acc[i];
}

// ---------------- O = Q*M*0.25 + fused attn-LIF (vth=0.5) --------------------
__global__ __launch_bounds__(128) void attn_o_lif_kernel(const __half* __restrict__ qkv,
                                                         const float* __restrict__ Mbuf,
                                                         __half* __restrict__ aspk) {
    __shared__ float Ms[HD * HD];
    const int nt = blockIdx.x, h = blockIdx.y, b = blockIdx.z;
    const int tid = threadIdx.x;
    const int n = nt * 128 + tid;
    float v[HD];
    #pragma unroll
    for (int e = 0; e < HD; e++) v[e] = 0.0f;
    for (int t = 0; t < 4; t++) {
        int tb = t * BATCH + b;
        for (int l = tid; l < HD * HD; l += 128)
            Ms[l] = Mbuf[((size_t)tb * NH + h) * (HD * HD) + l];
        __syncthreads();
        if (n < N_SP) {
            const __half* Qp = qkv + ((size_t)tb * N_SP + n) * QKV_M + h * HD;
            float q[HD];
            #pragma unroll
            for (int d = 0; d < HD; d++) q[d] = __half2float(Qp[d]);
            __half* Op = aspk + ((size_t)tb * N_SP + n) * C_DIM + h * HD;
            #pragma unroll 4
            for (int e = 0; e < HD; e++) {
                float s = 0.0f;
                #pragma unroll
                for (int d = 0; d < HD; d++) s += q[d] * Ms[d * HD + e];
                float x = s * 0.25f;
                float ve = v[e];
                ve = __fadd_rn(ve, __fmul_rn(__fsub_rn(x, ve), 0.5f));
                float sp = (ve >= 0.5f) ? 1.0f : 0.0f;
                Op[e] = __float2half_rn(sp);
                v[e] = (sp != 0.0f) ? 0.0f : ve;
            }
        }
        __syncthreads();
    }
}

// ---------------- x1 = x + proj_spk -----------------------------------------
__global__ void x1_kernel(const float* __restrict__ x, const __half* __restrict__ pspk,
                          float* __restrict__ x1f,
                          __half* __restrict__ x1h, __half* __restrict__ x1l) {
    __shared__ float s[32][33];
    int tb = blockIdx.z, c0 = blockIdx.x * 32, n0 = blockIdx.y * 32;
    int tx = threadIdx.x, ty = threadIdx.y;
    #pragma unroll
    for (int i = 0; i < 4; i++) {
        int nl = ty + i * 8, n = n0 + nl;
        s[nl][tx] = (n < N_SP)
            ? __half2float(pspk[((size_t)tb * N_SP + n) * C_DIM + c0 + tx]) : 0.0f;
    }
    __syncthreads();
    #pragma unroll
    for (int i = 0; i < 4; i++) {
        int cl = ty + i * 8, n = n0 + tx;
        if (n < N_SP) {
            size_t xi = ((size_t)tb * C_DIM + c0 + cl) * N_SP + n;
            float val = x[xi] + s[tx][cl];
            x1f[xi] = val;
            s[tx][cl] = val;
        }
    }
    __syncthreads();
    #pragma unroll
    for (int i = 0; i < 4; i++) {
        int nl = ty + i * 8, n = n0 + nl;
        if (n < N_SP) {
            float val = s[nl][tx];
            __half h = __float2half_rn(val);
            size_t d = ((size_t)tb * N_SP + n) * C_DIM + c0 + tx;
            x1h[d] = h;
            x1l[d] = __float2half_rn(val - __half2float(h));
        }
    }
}

// ---------------- out = x1f + mspk^T ----------------------------------------
__global__ void final_kernel(const float* __restrict__ x1f, const __half* __restrict__ mspk,
                             float* __restrict__ out) {
    __shared__ float s[32][33];
    int tb = blockIdx.z, c0 = blockIdx.x * 32, n0 = blockIdx.y * 32;
    int tx = threadIdx.x, ty = threadIdx.y;
    #pragma unroll
    for (int i = 0; i < 4; i++) {
        int nl = ty + i * 8, n = n0 + nl;
        s[nl][tx] = (n < N_SP)
            ? __half2float(mspk[((size_t)tb * N_SP + n) * C_DIM + c0 + tx]) : 0.0f;
    }
    __syncthreads();
    #pragma unroll
    for (int i = 0; i < 4; i++) {
        int cl = ty + i * 8, n = n0 + tx;
        if (n < N_SP) {
            size_t xi = ((size_t)tb * C_DIM + c0 + cl) * N_SP + n;
            out[xi] = x1f[xi] + s[tx][cl];
        }
    }
}

// ---------------------------------------------------------------------------
extern "C" void kernel_launch(void* const* d_in, const int* in_sizes, int n_in,
                              void* d_out, int out_size) {
    const float* x      = (const float*)d_in[0];
    const float* q_w    = (const float*)d_in[1];
    const float* k_w    = (const float*)d_in[2];
    const float* v_w    = (const float*)d_in[3];
    const float* q_bn   = (const float*)d_in[4];
    const float* k_bn   = (const float*)d_in[5];
    const float* v_bn   = (const float*)d_in[6];
    const float* proj_w = (const float*)d_in[7];
    const float* proj_b = (const float*)d_in[8];
    const float* proj_bn= (const float*)d_in[9];
    const float* fc1_w  = (const float*)d_in[10];
    const float* fc1_b  = (const float*)d_in[11];
    const float* fc1_bn = (const float*)d_in[12];
    const float* fc2_w  = (const float*)d_in[13];
    const float* fc2_b  = (const float*)d_in[14];
    const float* fc2_bn = (const float*)d_in[15];
    float* out = (float*)d_out;

    cudaFuncSetAttribute(gemm_hmma, cudaFuncAttributeMaxDynamicSharedMemorySize, GSMEM);

    __half *xh, *xl, *wqkvh, *wqkvl, *wph, *wpl, *w1h, *w1l, *w2h, *w2l;
    __half *qkv, *aspk, *pspk, *x1h, *x1l, *hspk, *mspk;
    float *offqkv, *offp, *off1, *off2, *Mb, *x1f, *pre;
    cudaGetSymbolAddress((void**)&pre, g_pre);
    cudaGetSymbolAddress((void**)&xh, g_xh);       cudaGetSymbolAddress((void**)&xl, g_xl);
    cudaGetSymbolAddress((void**)&wqkvh, g_wqkvh); cudaGetSymbolAddress((void**)&wqkvl, g_wqkvl);
    cudaGetSymbolAddress((void**)&wph, g_wph);     cudaGetSymbolAddress((void**)&wpl, g_wpl);
    cudaGetSymbolAddress((void**)&w1h, g_w1h);     cudaGetSymbolAddress((void**)&w1l, g_w1l);
    cudaGetSymbolAddress((void**)&w2h, g_w2h);     cudaGetSymbolAddress((void**)&w2l, g_w2l);
    cudaGetSymbolAddress((void**)&offqkv, g_offqkv); cudaGetSymbolAddress((void**)&offp, g_offp);
    cudaGetSymbolAddress((void**)&off1, g_off1);   cudaGetSymbolAddress((void**)&off2, g_off2);
    cudaGetSymbolAddress((void**)&qkv, g_qkv);     cudaGetSymbolAddress((void**)&Mb, g_M);
    cudaGetSymbolAddress((void**)&aspk, g_aspk);   cudaGetSymbolAddress((void**)&pspk, g_pspk);
    cudaGetSymbolAddress((void**)&x1h, g_x1h);     cudaGetSymbolAddress((void**)&x1l, g_x1l);
    cudaGetSymbolAddress((void**)&x1f, g_x1f);
    cudaGetSymbolAddress((void**)&hspk, g_hspk);   cudaGetSymbolAddress((void**)&mspk, g_mspk);

    dim3 tb32(32, 8);
    dim3 tgrid(C_DIM / 32, (N_SP + 31) / 32, TB);

    int wb3 = (3 * C_DIM * C_DIM + 255) / 256;
    wsplit3_kernel<<<wb3, 256>>>(q_w, k_w, v_w, q_bn, k_bn, v_bn, wqkvh, wqkvl, offqkv);
    int wb = (C_DIM * C_DIM + 255) / 256;
    wsplit_kernel<<<wb, 256>>>(proj_w, proj_bn, proj_b, wph, wpl, offp, C_DIM, C_DIM, 0);
    int wb1 = (H_DIM * C_DIM + 255) / 256;
    wsplit_kernel<<<wb1, 256>>>(fc1_w, fc1_bn, fc1_b, w1h, w1l, off1, H_DIM, C_DIM, 0);
    wsplit_kernel<<<wb1, 256>>>(fc2_w, fc2_bn, fc2_b, w2h, w2l, off2, C_DIM, H_DIM, 0);
    xsplit_kernel<<<tgrid, tb32>>>(x, xh, xl);

    const int eptQ = BATCH * N_SP * QKV_M;
    const int eptC = BATCH * N_SP * C_DIM;
    const int eptH = BATCH * N_SP * H_DIM;

    // flat-row GEMMs: grid (196, Mtot/128) — zero padding waste
    gemm_hmma<<<dim3(NTILES, QKV_M / 128), 256, GSMEM>>>(xh, xl, wqkvh, wqkvl, offqkv, pre,
                                                         C_DIM, QKV_M, 2);
    lif_kernel<<<(eptQ / 2 + 255) / 256, 256>>>(pre, qkv, eptQ, 1.0f);

    attn_m_kernel<<<TB * NH, 256>>>(qkv, Mb);
    attn_o_lif_kernel<<<dim3(7, NH, BATCH), 128>>>(qkv, Mb, aspk);

    gemm_hmma<<<dim3(NTILES, C_DIM / 128), 256, GSMEM>>>(aspk, aspk, wph, wpl, offp, pre,
                                                         C_DIM, C_DIM, 1);
    lif_kernel<<<(eptC / 2 + 255) / 256, 256>>>(pre, pspk, eptC, 1.0f);

    x1_kernel<<<tgrid, tb32>>>(x, pspk, x1f, x1h, x1l);

    gemm_hmma<<<dim3(NTILES, H_DIM / 128), 256, GSMEM>>>(x1h, x1l, w1h, w1l, off1, pre,
                                                         C_DIM, H_DIM, 2);
    lif_kernel<<<(eptH / 2 + 255) / 256, 256>>>(pre, hspk, eptH, 1.0f);

    gemm_hmma<<<dim3(NTILES, C_DIM / 128), 256, GSMEM>>>(hspk, hspk, w2h, w2l, off2, pre,
                                                         H_DIM, C_DIM, 1);
    lif_kernel<<<(eptC / 2 + 255) / 256, 256>>>(pre, mspk, eptC, 1.0f);

    final_kernel<<<tgrid, tb32>>>(x1f, mspk, out);
}